// round 2
// baseline (speedup 1.0000x reference)
#include <cuda_runtime.h>
#include <cstdint>

// CTC prefix beam search decoder, exact replication of the JAX reference.
// B=1024 independent chains; one warp per batch element, warp-synchronous.
// State per warp lives in shared memory; prefixes reconstructed by backtrace.

#define BATCH 1024
#define TT    128
#define CCC   63
#define VVV   62
#define WW    8
#define NCAND (WW + WW * VVV)   // 504
#define NEGF  (-1e30f)
#define HB1C  1000003u
#define HB2C  2654435761u
#define WARPS_PER_BLOCK 4

struct WarpState {
    float lp[64];                       // log-softmax frame (63 used)
    float pb[WW], pnb[WW], ptot[WW];    // beam log-probs
    float spb[WW], spnb[WW];            // stay candidate pb/pnb
    float mpnb[WW];                     // merged stay pnb
    float mgpnb[WW];                    // merge partner e_pnb
    unsigned int h1[WW], h2[WW];        // rolling hashes (prefix identity)
    int last[WW], len[WW];
    int dupf[WW], mgf[WW];
    int sel_idx[WW];
    float sel_sc[WW];
    unsigned short hist[TT * WW];       // (parent<<8) | (char+1); char=-1 -> 0
};

// jnp.logaddexp: max + log1p(exp(-|a-b|))
__device__ __forceinline__ float lax_logaddexp(float a, float b) {
    float m = fmaxf(a, b);
    return m + log1pf(expf(-fabsf(a - b)));
}

// reference seg_lse for a 2-element segment:
// m = max; s = exp(a-m)+exp(b-m); log(max(s,1e-30)) + m
__device__ __forceinline__ float seg_lse2(float a, float b) {
    float m = fmaxf(a, b);
    float s = expf(a - m) + expf(b - m);
    return logf(fmaxf(s, 1e-30f)) + m;
}

// float -> monotonic unsigned mapping
__device__ __forceinline__ unsigned ord_of_float(float f) {
    unsigned u = __float_as_uint(f);
    return (u & 0x80000000u) ? ~u : (u | 0x80000000u);
}
__device__ __forceinline__ float float_of_ord(unsigned u) {
    return __uint_as_float((u & 0x80000000u) ? (u & 0x7fffffffu) : ~u);
}

__global__ void __launch_bounds__(32 * WARPS_PER_BLOCK, 8)
ctc_beam_kernel(const float* __restrict__ logits, float* __restrict__ out) {
    __shared__ WarpState ws_all[WARPS_PER_BLOCK];
    const int wip  = threadIdx.x >> 5;
    const int lane = threadIdx.x & 31;
    const int b    = blockIdx.x * WARPS_PER_BLOCK + wip;
    if (b >= BATCH) return;
    WarpState& ws = ws_all[wip];

    // initial state: beam 0 alive (pb=0), beams 1..7 dead, all hash (1,1)
    if (lane < WW) {
        ws.h1[lane] = 1u; ws.h2[lane] = 1u;
        ws.pb[lane]  = (lane == 0) ? 0.0f : NEGF;
        ws.pnb[lane] = NEGF;
        ws.last[lane] = -1;
        ws.len[lane]  = 0;
    }
    __syncwarp();

    const float* base = logits + (size_t)b * TT * CCC;

    for (int t = 0; t < TT; ++t) {
        // ---- 1. log_softmax of frame t (63 classes, blank = 62) ----
        const float* fr = base + t * CCC;
        float x0 = fr[lane];
        float x1 = (lane < CCC - 32) ? fr[lane + 32] : __uint_as_float(0xff800000u);
        float mx = fmaxf(x0, x1);
        #pragma unroll
        for (int off = 16; off; off >>= 1)
            mx = fmaxf(mx, __shfl_xor_sync(0xffffffffu, mx, off));
        float e0 = expf(x0 - mx);
        float e1 = (lane < CCC - 32) ? expf(x1 - mx) : 0.0f;
        float sm = e0 + e1;
        #pragma unroll
        for (int off = 16; off; off >>= 1)
            sm += __shfl_xor_sync(0xffffffffu, sm, off);
        float lse = logf(sm);
        ws.lp[lane] = x0 - mx - lse;
        if (lane < CCC - 32) ws.lp[lane + 32] = x1 - mx - lse;
        __syncwarp();

        // ---- 2. per-beam prep: dup detection, stay candidates ----
        if (lane < WW) {
            int j = lane;
            unsigned mh1 = ws.h1[j], mh2 = ws.h2[j];
            bool dup = false;
            for (int k2 = 0; k2 < j; ++k2)
                dup |= (ws.h1[k2] == mh1 && ws.h2[k2] == mh2);
            ws.dupf[j] = dup ? 1 : 0;
            float pbj = ws.pb[j], pnbj = ws.pnb[j];
            float pt = lax_logaddexp(pbj, pnbj);
            ws.ptot[j] = pt;
            ws.spb[j]  = pt + ws.lp[VVV];              // blank emission
            int lj = ws.last[j];
            ws.spnb[j] = (lj >= 0) ? (pnbj + ws.lp[lj]) : NEGF;
            ws.mgf[j] = 0;
        }
        __syncwarp();

        // ---- 3. extend candidates + merge detection ----
        // candidate idx = lane + 32*slot; idx<8 = stay, else extend (i = e/62, c = e%62)
        float cs[16];
        #pragma unroll
        for (int s2 = 0; s2 < 16; ++s2) {
            int idx = lane + 32 * s2;
            float sc = -3.402823466e38f;   // invalid sentinel (below NEG)
            if (idx >= WW && idx < NCAND) {
                int e = idx - WW;
                int i = e / VVV;
                int c = e - i * VVV;
                if (ws.dupf[i]) {
                    sc = NEGF;  // duplicate beam's extends are non-representatives
                } else {
                    float basev = (c == ws.last[i]) ? ws.pb[i] : ws.ptot[i];
                    float ep = basev + ws.lp[c];
                    unsigned nh1 = ws.h1[i] * HB1C + (unsigned)(c + 1);
                    unsigned nh2 = ws.h2[i] * HB2C + (unsigned)(c + 1);
                    int mj = -1;
                    #pragma unroll
                    for (int j2 = 0; j2 < WW; ++j2)
                        if (!ws.dupf[j2] && ws.h1[j2] == nh1 && ws.h2[j2] == nh2)
                            mj = j2;
                    if (mj >= 0) {
                        // merges into stay mj (unique partner: prefix_mj = prefix_i + c)
                        ws.mgpnb[mj] = ep;
                        ws.mgf[mj] = 1;
                        sc = NEGF;  // non-representative slot
                    } else {
                        sc = ep;    // logaddexp(NEG, ep) == ep exactly in fp32
                    }
                }
            }
            cs[s2] = sc;
        }
        __syncwarp();

        // ---- 4. finalize stay candidate scores ----
        if (lane < WW) {
            int j = lane;
            if (ws.dupf[j]) {
                cs[0] = NEGF;
                ws.mpnb[j] = ws.spnb[j];
            } else {
                float mn = ws.mgf[j] ? seg_lse2(ws.spnb[j], ws.mgpnb[j]) : ws.spnb[j];
                ws.mpnb[j] = mn;
                cs[0] = lax_logaddexp(ws.spb[j], mn);
            }
        }

        // ---- 5. top-8 selection (8 warp-argmax passes over precomputed keys) ----
        // key = (ordered_score << 10) | (1023 - idx): ties -> lowest idx (ties only
        // occur between exact-NEG candidates which are never selected).
        unsigned long long key[16];
        #pragma unroll
        for (int s2 = 0; s2 < 16; ++s2) {
            int idx = lane + 32 * s2;
            key[s2] = ((unsigned long long)ord_of_float(cs[s2]) << 10)
                      | (unsigned)(1023 - idx);
            if (idx >= NCAND) key[s2] = 0ull;
        }
        for (int k2 = 0; k2 < WW; ++k2) {
            unsigned long long best = 0ull;
            #pragma unroll
            for (int s2 = 0; s2 < 16; ++s2)
                if (key[s2] > best) best = key[s2];
            #pragma unroll
            for (int off = 16; off; off >>= 1) {
                unsigned long long o = __shfl_xor_sync(0xffffffffu, best, off);
                if (o > best) best = o;
            }
            int widx = 1023 - (int)(best & 1023u);
            if (lane == (widx & 31)) key[widx >> 5] = 0ull;  // remove winner
            if (lane == 0) {
                ws.sel_idx[k2] = widx;
                ws.sel_sc[k2]  = float_of_ord((unsigned)(best >> 10));
            }
        }
        __syncwarp();

        // ---- 6. commit new beam state ----
        unsigned nh1v = 0, nh2v = 0;
        float npb = 0.f, npnb = 0.f;
        int nlast = 0, nlen = 0;
        unsigned short hrec = 0;
        if (lane < WW) {
            int idx = ws.sel_idx[lane];
            float sc = ws.sel_sc[lane];
            bool alive = sc > 0.5f * NEGF;
            if (idx < WW) {            // stay: keep beam idx's prefix
                int j = idx;
                npb = ws.spb[j]; npnb = ws.mpnb[j];
                nh1v = ws.h1[j]; nh2v = ws.h2[j];
                nlast = ws.last[j]; nlen = ws.len[j];
                hrec = (unsigned short)((j << 8) | 0);
            } else {                   // extend: parent i, char c
                int e = idx - WW;
                int i = e / VVV;
                int c = e - i * VVV;
                npb = NEGF; npnb = sc;  // unmerged extend score == e_pnb
                nh1v = ws.h1[i] * HB1C + (unsigned)(c + 1);
                nh2v = ws.h2[i] * HB2C + (unsigned)(c + 1);
                nlast = c; nlen = ws.len[i] + 1;
                hrec = (unsigned short)((i << 8) | (c + 1));
            }
            if (!alive) { npb = NEGF; npnb = NEGF; }
        }
        __syncwarp();
        if (lane < WW) {
            ws.pb[lane] = npb; ws.pnb[lane] = npnb;
            ws.h1[lane] = nh1v; ws.h2[lane] = nh2v;
            ws.last[lane] = nlast; ws.len[lane] = nlen;
            ws.hist[t * WW + lane] = hrec;
        }
        __syncwarp();
    }

    // ---- outputs: decoded [B*128] then lengths [B] then prob [B], all f32 ----
    float* dec = out + (size_t)b * TT;
    #pragma unroll
    for (int s2 = 0; s2 < 4; ++s2)
        dec[lane + 32 * s2] = -1.0f;
    __syncwarp();
    if (lane == 0) {
        int cur = 0;
        int pos = ws.len[0] - 1;
        for (int tt = TT - 1; tt >= 0; --tt) {
            unsigned short h = ws.hist[tt * WW + cur];
            int c = (int)(h & 0xFF) - 1;
            cur = h >> 8;
            if (c >= 0) dec[pos--] = (float)c;
        }
        out[(size_t)BATCH * TT + b] = (float)ws.len[0];
        out[(size_t)BATCH * TT + BATCH + b] =
            expf(lax_logaddexp(ws.pb[0], ws.pnb[0]));
    }
}

extern "C" void kernel_launch(void* const* d_in, const int* in_sizes, int n_in,
                              void* d_out, int out_size) {
    const float* logits = (const float*)d_in[0];
    float* out = (float*)d_out;
    ctc_beam_kernel<<<BATCH / WARPS_PER_BLOCK, 32 * WARPS_PER_BLOCK>>>(logits, out);
}

// round 4
// speedup vs baseline: 2.0854x; 2.0854x over previous
#include <cuda_runtime.h>
#include <cstdint>

// CTC prefix beam search decoder — exact replication of the JAX reference.
// One warp per batch element (1024 chains), warp-synchronous, state in shared.
// Round 3: no reg cap (kills spills), inverted merge detection (hash-difference),
// REDUX-based top-8 selection, frame prefetch.

#define BATCH 1024
#define TT    128
#define CCC   63
#define VVV   62
#define WW    8
#define NEGF  (-1e30f)
#define HB1C  1000003u
#define HB2C  2654435761u
#define WPB   4

struct WarpState {
    float lp[64];                         // log-softmax frame
    float pb[WW], pnb[WW], ptot[WW];
    float spb[WW], spnb[WW], mpnb[WW];
    unsigned h1[WW], h2[WW];
    int last[WW], len[WW], dupf[WW];
    unsigned mml[WW], mmh[WW];            // merge mask bits [0..31], [32..61]
    int sel_idx[WW];
    unsigned sel_ord[WW];
    unsigned short hist[TT * WW];         // (parent<<8) | (char+1)
};

__device__ __forceinline__ float lax_logaddexp(float a, float b) {
    float m = fmaxf(a, b);
    return m + log1pf(expf(-fabsf(a - b)));
}
// reference seg_lse for a 2-element segment
__device__ __forceinline__ float seg_lse2(float a, float b) {
    float m = fmaxf(a, b);
    float s = expf(a - m) + expf(b - m);
    return logf(fmaxf(s, 1e-30f)) + m;
}
__device__ __forceinline__ unsigned ord_of_float(float f) {
    unsigned u = __float_as_uint(f);
    return (u & 0x80000000u) ? ~u : (u | 0x80000000u);
}
__device__ __forceinline__ float float_of_ord(unsigned u) {
    return __uint_as_float((u & 0x80000000u) ? (u & 0x7fffffffu) : ~u);
}

__global__ void ctc_beam_kernel(const float* __restrict__ logits,
                                float* __restrict__ out) {
    __shared__ WarpState ws_all[WPB];
    const int wip  = threadIdx.x >> 5;
    const int lane = threadIdx.x & 31;
    const int b    = blockIdx.x * WPB + wip;
    WarpState& ws = ws_all[wip];

    if (lane < WW) {
        ws.h1[lane] = 1u; ws.h2[lane] = 1u;
        ws.pb[lane]  = (lane == 0) ? 0.0f : NEGF;
        ws.pnb[lane] = NEGF;
        ws.last[lane] = -1;
        ws.len[lane]  = 0;
    }
    __syncwarp();

    const float* base = logits + (size_t)b * TT * CCC;
    const float NINF = __int_as_float(0xff800000);

    // prefetch frame 0
    float x0 = base[lane];
    float x1 = (lane < 31) ? base[lane + 32] : NINF;

    for (int t = 0; t < TT; ++t) {
        float cx0 = x0, cx1 = x1;
        // prefetch next frame early: DRAM latency hides under this step's work
        if (t + 1 < TT) {
            const float* nf = base + (t + 1) * CCC;
            x0 = nf[lane];
            x1 = (lane < 31) ? nf[lane + 32] : NINF;
        }

        // ---- 1. log_softmax (max via redux: exact; sum via same shfl tree) ----
        unsigned mo = __reduce_max_sync(0xffffffffu,
                                        ord_of_float(fmaxf(cx0, cx1)));
        float mx = float_of_ord(mo);
        float e0 = expf(cx0 - mx);
        float e1 = (lane < 31) ? expf(cx1 - mx) : 0.0f;
        float sm = e0 + e1;
        #pragma unroll
        for (int off = 16; off; off >>= 1)
            sm += __shfl_xor_sync(0xffffffffu, sm, off);
        float lse = logf(sm);
        ws.lp[lane] = cx0 - mx - lse;
        if (lane < 31) ws.lp[lane + 32] = cx1 - mx - lse;
        __syncwarp();

        // ---- 2a. per-beam prep (lanes<8): dup flag, stay candidates ----
        unsigned mh1 = 0, mh2 = 0;
        float spbj = 0.f, spj = 0.f;
        bool dup = false;
        if (lane < WW) {
            mh1 = ws.h1[lane]; mh2 = ws.h2[lane];
            for (int k2 = 0; k2 < lane; ++k2)
                dup |= (ws.h1[k2] == mh1 && ws.h2[k2] == mh2);
            ws.dupf[lane] = dup ? 1 : 0;
            float pbj = ws.pb[lane], pnbj = ws.pnb[lane];
            float pt = lax_logaddexp(pbj, pnbj);
            ws.ptot[lane] = pt;
            spbj = pt + ws.lp[VVV];
            ws.spb[lane] = spbj;
            int lj = ws.last[lane];
            spj = (lj >= 0) ? (pnbj + ws.lp[lj]) : NEGF;
            ws.spnb[lane] = spj;
        }
        __syncwarp();

        // ---- 2b. inverted merge detection: each stay j finds its unique
        // parent (i,c) with hash(prefix_i + c) == hash(prefix_j).
        // Condition identical to forward per-candidate hash compare. ----
        unsigned s_st = 0u;
        if (lane < WW) {
            int msrc = -1;
            if (!dup) {
                #pragma unroll
                for (int i = 0; i < WW; ++i) {
                    if (!ws.dupf[i]) {
                        unsigned c1 = mh1 - ws.h1[i] * HB1C - 1u;
                        if (c1 < (unsigned)VVV &&
                            mh2 == ws.h2[i] * HB2C + c1 + 1u)
                            msrc = i * 64 + (int)c1;
                    }
                }
            }
            // build merge masks via shfl among lanes 0..7
            unsigned mml = 0u, mmh = 0u;
            #pragma unroll
            for (int jj = 0; jj < WW; ++jj) {
                int ms = __shfl_sync(0x000000ffu, msrc, jj);
                if (ms >= 0 && (ms >> 6) == lane) {
                    int c = ms & 63;
                    if (c < 32) mml |= 1u << c; else mmh |= 1u << (c - 32);
                }
            }
            ws.mml[lane] = mml; ws.mmh[lane] = mmh;
            // merged stay pnb
            float mn = spj;
            if (msrc >= 0) {
                int i = msrc >> 6, c = msrc & 63;
                float bv = (c == ws.last[i]) ? ws.pb[i] : ws.ptot[i];
                mn = seg_lse2(spj, bv + ws.lp[c]);
            }
            ws.mpnb[lane] = mn;
            float cs0 = dup ? NEGF : lax_logaddexp(spbj, mn);
            s_st = ord_of_float(cs0);
        }
        __syncwarp();

        // ---- 3. extend candidate scores, ordered-u32, per-beam loop ----
        // slot i   : candidate (beam i, class c = lane)       idx = 8 + i*62 + lane
        // slot i+8 : candidate (beam i, class c = lane + 32)  idx = 8 + i*62 + lane+32
        float c_lp0 = ws.lp[lane];
        float c_lp1 = (lane < 30) ? ws.lp[lane + 32] : 0.0f;
        unsigned s16[16];
        #pragma unroll
        for (int i = 0; i < WW; ++i) {
            int   li = ws.last[i];
            float pbi = ws.pb[i], pti = ws.ptot[i];
            int   dfi = ws.dupf[i];
            unsigned mml = ws.mml[i], mmh = ws.mmh[i];
            // lo: c = lane (always < 62)
            {
                float sc = ((lane == li) ? pbi : pti) + c_lp0;
                if (dfi || ((mml >> lane) & 1u)) sc = NEGF;
                s16[i] = ord_of_float(sc);
            }
            // hi: c = lane + 32 (valid if lane < 30)
            {
                int c = lane + 32;
                float sc = ((c == li) ? pbi : pti) + c_lp1;
                if (dfi || ((mmh >> lane) & 1u)) sc = NEGF;
                s16[i + 8] = (lane < 30) ? ord_of_float(sc) : 0u;
            }
        }

        // ---- 4. top-8 via 8 argmax passes (REDUX), tie-break lowest idx ----
        // x = 1023 - idx; idx(slot s2) = 8 + (s2&7)*62 + lane + ((s2&8)?32:0)
        #define XCONST(s2) (unsigned)(1015 - 62 * ((s2) & 7) - (((s2) & 8) ? 32 : 0))
        unsigned bs, bx;
        #define RESCAN() do {                                                  \
            bs = s_st; bx = (lane < WW) ? (unsigned)(1023 - lane) : 0u;        \
            _Pragma("unroll")                                                  \
            for (int s2 = 0; s2 < 16; ++s2) {                                  \
                unsigned xx = XCONST(s2) - (unsigned)lane;                     \
                if (s16[s2] > bs || (s16[s2] == bs && xx > bx)) {              \
                    bs = s16[s2]; bx = xx;                                     \
                }                                                              \
            }                                                                  \
        } while (0)
        RESCAN();
        #pragma unroll
        for (int k2 = 0; k2 < WW; ++k2) {
            unsigned m  = __reduce_max_sync(0xffffffffu, bs);
            unsigned tx = (bs == m) ? bx : 0u;
            unsigned mxi = __reduce_max_sync(0xffffffffu, tx);
            int widx = 1023 - (int)mxi;
            if (lane == 0) { ws.sel_idx[k2] = widx; ws.sel_ord[k2] = m; }
            // clear winner's slot (register array, static predicated writes)
            if (widx < WW) {
                if (lane == widx) s_st = 0u;
            } else {
                int e = widx - WW;
                int i2 = e / VVV;
                int c2 = e - VVV * i2;
                if (lane == (c2 & 31)) {
                    int slot = i2 + ((c2 & 32) ? 8 : 0);
                    #pragma unroll
                    for (int s2 = 0; s2 < 16; ++s2)
                        if (s2 == slot) s16[s2] = 0u;
                }
            }
            RESCAN();
        }
        __syncwarp();

        // ---- 5. commit new beam state ----
        unsigned nh1v = 0, nh2v = 0;
        float npb = 0.f, npnb = 0.f;
        int nlast = 0, nlen = 0;
        unsigned short hrec = 0;
        if (lane < WW) {
            int idx = ws.sel_idx[lane];
            float sc = float_of_ord(ws.sel_ord[lane]);
            bool alive = sc > 0.5f * NEGF;
            if (idx < WW) {            // stay
                int j = idx;
                npb = ws.spb[j]; npnb = ws.mpnb[j];
                nh1v = ws.h1[j]; nh2v = ws.h2[j];
                nlast = ws.last[j]; nlen = ws.len[j];
                hrec = (unsigned short)(j << 8);
            } else {                   // extend
                int e = idx - WW;
                int i = e / VVV;
                int c = e - VVV * i;
                npb = NEGF; npnb = sc;
                nh1v = ws.h1[i] * HB1C + (unsigned)(c + 1);
                nh2v = ws.h2[i] * HB2C + (unsigned)(c + 1);
                nlast = c; nlen = ws.len[i] + 1;
                hrec = (unsigned short)((i << 8) | (c + 1));
            }
            if (!alive) { npb = NEGF; npnb = NEGF; }
        }
        __syncwarp();
        if (lane < WW) {
            ws.pb[lane] = npb; ws.pnb[lane] = npnb;
            ws.h1[lane] = nh1v; ws.h2[lane] = nh2v;
            ws.last[lane] = nlast; ws.len[lane] = nlen;
            ws.hist[t * WW + lane] = hrec;
        }
        __syncwarp();
    }

    // ---- outputs: decoded [B*128], lengths [B], prob [B], all f32 ----
    float* dec = out + (size_t)b * TT;
    #pragma unroll
    for (int s2 = 0; s2 < 4; ++s2)
        dec[lane + 32 * s2] = -1.0f;
    __syncwarp();
    if (lane == 0) {
        int cur = 0;
        int pos = ws.len[0] - 1;
        for (int tt = TT - 1; tt >= 0; --tt) {
            unsigned short h = ws.hist[tt * WW + cur];
            int c = (int)(h & 0xFF) - 1;
            cur = h >> 8;
            if (c >= 0) dec[pos--] = (float)c;
        }
        out[(size_t)BATCH * TT + b] = (float)ws.len[0];
        out[(size_t)BATCH * TT + BATCH + b] =
            expf(lax_logaddexp(ws.pb[0], ws.pnb[0]));
    }
}

extern "C" void kernel_launch(void* const* d_in, const int* in_sizes, int n_in,
                              void* d_out, int out_size) {
    const float* logits = (const float*)d_in[0];
    float* out = (float*)d_out;
    ctc_beam_kernel<<<BATCH / WPB, 32 * WPB>>>(logits, out);
}

// round 5
// speedup vs baseline: 3.5260x; 1.6908x over previous
#include <cuda_runtime.h>
#include <cstdint>

// CTC prefix beam search — bit-exact vs JAX reference.
// One warp per batch element; ALL state in registers + shfl; no syncwarp in loop.

#define BATCH 1024
#define TT    128
#define CCC   63
#define VVV   62
#define WW    8
#define NEGF  (-1e30f)
#define HB1C  1000003u
#define HB2C  2654435761u
#define WPB   4
#define FULL  0xffffffffu

typedef unsigned long long u64;
typedef unsigned int u32;

__device__ __forceinline__ float lax_logaddexp(float a, float b) {
    float m = fmaxf(a, b);
    return m + log1pf(expf(-fabsf(a - b)));
}
__device__ __forceinline__ float seg_lse2(float a, float b) {
    float m = fmaxf(a, b);
    float s = expf(a - m) + expf(b - m);
    return logf(fmaxf(s, 1e-30f)) + m;
}
__device__ __forceinline__ u32 ord_of_float(float f) {
    u32 u = __float_as_uint(f);
    return (u & 0x80000000u) ? ~u : (u | 0x80000000u);
}
__device__ __forceinline__ float float_of_ord(u32 u) {
    return __uint_as_float((u & 0x80000000u) ? (u & 0x7fffffffu) : ~u);
}
__device__ __forceinline__ u64 kmax(u64 a, u64 b) { return a > b ? a : b; }

__global__ void ctc_beam_kernel(const float* __restrict__ logits,
                                float* __restrict__ out) {
    __shared__ unsigned short hist[WPB][TT * WW];  // (parent<<8)|(char+1)
    const int wip  = threadIdx.x >> 5;
    const int lane = threadIdx.x & 31;
    const int b    = blockIdx.x * WPB + wip;
    const float* base = logits + (size_t)b * TT * CCC;
    const float NINF = __int_as_float(0xff800000);

    // beam state (valid on lanes 0..7; lane j == beam j)
    u32 bm_h1 = 1u, bm_h2 = 1u;
    float bm_pb  = (lane == 0) ? 0.0f : NEGF;
    float bm_pnb = NEGF;
    int bm_last = -1, bm_len = 0;
    float bm_spb = NEGF, bm_mpnb = NEGF;

    const u32 Mlow = ((u32)lane << 5) - ((u32)lane << 10);
    const u32 ordDeadThr = ord_of_float(0.5f * NEGF);

    // per-lane selection results (lane k holds pass-k winner)
    u32 sel_m = 0u, sel_lo = 0u;

    // softmax frame 0
    float lp0, lp1;
    {
        float cx0 = base[lane];
        float cx1 = (lane < 31) ? base[lane + 32] : NINF;
        u32 mo = __reduce_max_sync(FULL, ord_of_float(fmaxf(cx0, cx1)));
        float mx = float_of_ord(mo);
        float e0 = expf(cx0 - mx);
        float e1 = (lane < 31) ? expf(cx1 - mx) : 0.0f;
        float sm = e0 + e1;
        #pragma unroll
        for (int off = 16; off; off >>= 1)
            sm += __shfl_xor_sync(FULL, sm, off);
        float lse = logf(sm);
        lp0 = cx0 - mx - lse;
        lp1 = cx1 - mx - lse;      // lane 31: garbage, never consumed
    }
    // prefetch frame 1
    float nx0 = base[CCC + lane];
    float nx1 = (lane < 31) ? base[CCC + lane + 32] : NINF;

    for (int t = 0; t < TT; ++t) {
        // ---- 2a: per-beam prep (lanes<8 meaningful; all lanes execute) ----
        float lpBlank = __shfl_sync(FULL, lp1, 30);   // class 62
        int ls = (bm_last >= 0) ? (bm_last & 31) : 0;
        float v0 = __shfl_sync(FULL, lp0, ls);
        float v1 = __shfl_sync(FULL, lp1, ls);
        float lpLast = (bm_last >= 32) ? v1 : v0;

        int dup = 0;
        #pragma unroll
        for (int k = 0; k < 7; ++k) {
            u32 hk1 = __shfl_sync(FULL, bm_h1, k);
            u32 hk2 = __shfl_sync(FULL, bm_h2, k);
            if (k < lane && hk1 == bm_h1 && hk2 == bm_h2) dup = 1;
        }
        float bm_ptot = lax_logaddexp(bm_pb, bm_pnb);
        bm_spb = bm_ptot + lpBlank;
        float bm_spnb = (bm_last >= 0) ? (bm_pnb + lpLast) : NEGF;

        // ---- 2b: inverted merge detection: stay j finds parent (i,c) ----
        int msrc = -1;
        #pragma unroll
        for (int i = 0; i < WW; ++i) {
            u32 ih1 = __shfl_sync(FULL, bm_h1, i);
            u32 ih2 = __shfl_sync(FULL, bm_h2, i);
            int idup = __shfl_sync(FULL, dup, i);
            u32 c1 = bm_h1 - ih1 * HB1C - 1u;
            if (!dup && !idup && c1 < (u32)VVV &&
                bm_h2 == ih2 * HB2C + c1 + 1u)
                msrc = i * 64 + (int)c1;
        }
        if (lane >= WW) msrc = -1;

        // kill masks: bit i set -> extend (beam i, class lane[/+32]) merged away
        u32 killLo = 0u, killHi = 0u;
        #pragma unroll
        for (int j = 0; j < WW; ++j) {
            int ms = __shfl_sync(FULL, msrc, j);
            if (ms >= 0) {
                int mi = ms >> 6, mc = ms & 63;
                if (mc == lane) killLo |= 1u << mi;
                if (mc == lane + 32) killHi |= 1u << mi;
            }
        }

        // merged stay pnb
        {
            int mi = (msrc >= 0) ? (msrc >> 6) : 0;
            int mc = (msrc >= 0) ? (msrc & 63) : 0;
            float mpbv = __shfl_sync(FULL, bm_pb, mi);
            float mptv = __shfl_sync(FULL, bm_ptot, mi);
            int   mlv  = __shfl_sync(FULL, bm_last, mi);
            float w0 = __shfl_sync(FULL, lp0, mc & 31);
            float w1 = __shfl_sync(FULL, lp1, mc & 31);
            float lpc = (mc >= 32) ? w1 : w0;
            float bv = ((mc == mlv) ? mpbv : mptv) + lpc;
            bm_mpnb = (msrc >= 0) ? seg_lse2(bm_spnb, bv) : bm_spnb;
        }

        // stay key (slot 16): idx = lane (<8)
        float cs0 = dup ? NEGF : lax_logaddexp(bm_spb, bm_mpnb);
        u64 key16 = (lane < WW)
            ? (((u64)ord_of_float(cs0) << 32) |
               (u32)(((1023u << 10) + 16u) + Mlow))
            : 0ull;

        // ---- 3: extend keys. slot i: c=lane; slot i+8: c=lane+32 ----
        u64 key[16];
        #pragma unroll
        for (int i = 0; i < WW; ++i) {
            int   ilast = __shfl_sync(FULL, bm_last, i);
            float ipb   = __shfl_sync(FULL, bm_pb, i);
            float ipt   = __shfl_sync(FULL, bm_ptot, i);
            int   idup  = __shfl_sync(FULL, dup, i);
            float sl = ((lane == ilast) ? ipb : ipt) + lp0;
            if (idup || ((killLo >> i) & 1u)) sl = NEGF;
            u32 lowl = (u32)(((u32)(1015 - 62 * i) << 10) + (u32)i) + Mlow;
            key[i] = ((u64)ord_of_float(sl) << 32) | lowl;
            float sh = ((lane + 32 == ilast) ? ipb : ipt) + lp1;
            if (idup || ((killHi >> i) & 1u)) sh = NEGF;
            u32 lowh = (u32)(((u32)(983 - 62 * i) << 10) + (u32)(i + 8)) + Mlow;
            u64 kh = ((u64)ord_of_float(sh) << 32) | lowh;
            key[i + 8] = (lane < 30) ? kh : 0ull;
        }

        // ---- 3.5: OVERLAP — softmax of frame t+1 + prefetch t+2 ----
        float lpn0, lpn1;
        {
            u32 mo = __reduce_max_sync(FULL, ord_of_float(fmaxf(nx0, nx1)));
            float mx = float_of_ord(mo);
            float e0 = expf(nx0 - mx);
            float e1 = (lane < 31) ? expf(nx1 - mx) : 0.0f;
            float sm = e0 + e1;
            #pragma unroll
            for (int off = 16; off; off >>= 1)
                sm += __shfl_xor_sync(FULL, sm, off);
            float lse = logf(sm);
            lpn0 = nx0 - mx - lse;
            lpn1 = nx1 - mx - lse;
        }
        {
            int tn = (t + 2 < TT) ? (t + 2) : (TT - 1);
            const float* nf = base + tn * CCC;
            nx0 = nf[lane];
            nx1 = (lane < 31) ? nf[lane + 32] : NINF;
        }

        // ---- 4: top-8 (tree local max on u64 keys + 2 REDUX per pass) ----
        #pragma unroll
        for (int k2 = 0; k2 < WW; ++k2) {
            u64 x0 = kmax(key[0], key[1]);
            u64 x1 = kmax(key[2], key[3]);
            u64 x2 = kmax(key[4], key[5]);
            u64 x3 = kmax(key[6], key[7]);
            u64 x4 = kmax(key[8], key[9]);
            u64 x5 = kmax(key[10], key[11]);
            u64 x6 = kmax(key[12], key[13]);
            u64 x7 = kmax(key[14], key[15]);
            u64 y0 = kmax(x0, x1), y1 = kmax(x2, x3);
            u64 y2 = kmax(x4, x5), y3 = kmax(x6, x7);
            u64 loc = kmax(kmax(kmax(y0, y1), kmax(y2, y3)), key16);
            u32 hi = (u32)(loc >> 32), lo = (u32)loc;
            u32 m  = __reduce_max_sync(FULL, hi);
            u32 tx = (hi == m) ? lo : 0u;
            u32 lw = __reduce_max_sync(FULL, tx);
            if (lane == k2) { sel_m = m; sel_lo = lw; }
            int wlane = (int)((lw >> 5) & 31u);
            int wslot = (int)(lw & 31u);
            if (lane == wlane) {        // zero the winner's score word
                #pragma unroll
                for (int s = 0; s < 16; ++s)
                    if (s == wslot) key[s] &= 0xffffffffull;
                if (wslot == 16) key16 &= 0xffffffffull;
            }
        }

        // ---- 5: commit (gathers via shfl from OLD beam regs) ----
        int idx  = 1023 - (int)(sel_lo >> 10);
        bool stay = idx < WW;
        int slot = (int)(sel_lo & 31u);
        int wl   = (int)((sel_lo >> 5) & 31u);
        int src  = stay ? idx : (slot & 7);
        int c    = wl + ((slot & 8) ? 32 : 0);
        u32 g_h1   = __shfl_sync(FULL, bm_h1, src);
        u32 g_h2   = __shfl_sync(FULL, bm_h2, src);
        int g_last = __shfl_sync(FULL, bm_last, src);
        int g_len  = __shfl_sync(FULL, bm_len, src);
        float g_spb  = __shfl_sync(FULL, bm_spb, src);
        float g_mpnb = __shfl_sync(FULL, bm_mpnb, src);
        if (lane < WW) {
            bool alive = sel_m > ordDeadThr;
            float score = float_of_ord(sel_m);
            float npb  = stay ? g_spb  : NEGF;
            float npnb = stay ? g_mpnb : score;
            if (!alive) { npb = NEGF; npnb = NEGF; }
            bm_pb = npb; bm_pnb = npnb;
            bm_h1 = stay ? g_h1 : (g_h1 * HB1C + (u32)(c + 1));
            bm_h2 = stay ? g_h2 : (g_h2 * HB2C + (u32)(c + 1));
            bm_last = stay ? g_last : c;
            bm_len  = g_len + (stay ? 0 : 1);
            hist[wip][t * WW + lane] = stay
                ? (unsigned short)(idx << 8)
                : (unsigned short)(((slot & 7) << 8) | (c + 1));
        }
        lp0 = lpn0; lp1 = lpn1;
    }

    // ---- outputs: decoded [B*128], lengths [B], prob [B], all f32 ----
    float* dec = out + (size_t)b * TT;
    #pragma unroll
    for (int s2 = 0; s2 < 4; ++s2)
        dec[lane + 32 * s2] = -1.0f;
    __syncwarp();
    int len0 = __shfl_sync(FULL, bm_len, 0);
    float pb0  = __shfl_sync(FULL, bm_pb, 0);
    float pnb0 = __shfl_sync(FULL, bm_pnb, 0);
    if (lane == 0) {
        int cur = 0;
        int pos = len0 - 1;
        for (int tt = TT - 1; tt >= 0; --tt) {
            unsigned short h = hist[wip][tt * WW + cur];
            int cc = (int)(h & 0xFF) - 1;
            cur = h >> 8;
            if (cc >= 0) dec[pos--] = (float)cc;
        }
        out[(size_t)BATCH * TT + b] = (float)len0;
        out[(size_t)BATCH * TT + BATCH + b] = expf(lax_logaddexp(pb0, pnb0));
    }
}

extern "C" void kernel_launch(void* const* d_in, const int* in_sizes, int n_in,
                              void* d_out, int out_size) {
    const float* logits = (const float*)d_in[0];
    float* out = (float*)d_out;
    ctc_beam_kernel<<<BATCH / WPB, 32 * WPB>>>(logits, out);
}

// round 7
// speedup vs baseline: 3.6119x; 1.0244x over previous
#include <cuda_runtime.h>
#include <cstdint>

// CTC prefix beam search — bit-exact vs JAX reference.
// One warp per batch element; all state in registers + shfl; no syncwarp in loop.
// R6/R7: pair-node tournament for top-8, ballot-based dup mask, overlapped shfl loops.

#define BATCH 1024
#define TT    128
#define CCC   63
#define VVV   62
#define WW    8
#define NEGF  (-1e30f)
#define HB1C  1000003u
#define HB2C  2654435761u
#define WPB   4
#define FULL  0xffffffffu

typedef unsigned long long u64;
typedef unsigned int u32;

__device__ __forceinline__ float lax_logaddexp(float a, float b) {
    float m = fmaxf(a, b);
    return m + log1pf(expf(-fabsf(a - b)));
}
__device__ __forceinline__ float seg_lse2(float a, float b) {
    float m = fmaxf(a, b);
    float s = expf(a - m) + expf(b - m);
    return logf(fmaxf(s, 1e-30f)) + m;
}
__device__ __forceinline__ u32 ord_of_float(float f) {
    u32 u = __float_as_uint(f);
    return (u & 0x80000000u) ? ~u : (u | 0x80000000u);
}
__device__ __forceinline__ float float_of_ord(u32 u) {
    return __uint_as_float((u & 0x80000000u) ? (u & 0x7fffffffu) : ~u);
}
__device__ __forceinline__ u64 kmax(u64 a, u64 b) { return a > b ? a : b; }

__global__ void ctc_beam_kernel(const float* __restrict__ logits,
                                float* __restrict__ out) {
    __shared__ unsigned short hist[WPB][TT * WW];  // (parent<<8)|(char+1)
    const int wip  = threadIdx.x >> 5;
    const int lane = threadIdx.x & 31;
    const int b    = blockIdx.x * WPB + wip;
    const float* base = logits + (size_t)b * TT * CCC;
    const float NINF = __int_as_float(0xff800000);

    // beam state (valid on lanes 0..7; lane j == beam j)
    u32 bm_h1 = 1u, bm_h2 = 1u;
    float bm_pb  = (lane == 0) ? 0.0f : NEGF;
    float bm_pnb = NEGF;
    int bm_last = -1, bm_len = 0;
    float bm_spb = NEGF, bm_mpnb = NEGF;

    const u32 Mlow = ((u32)lane << 5) - ((u32)lane << 10);
    const u32 ordDeadThr = ord_of_float(0.5f * NEGF);

    u32 sel_m = 0u, sel_lo = 0u;   // lane k holds pass-k winner

    // softmax frame 0
    float lp0, lp1;
    {
        float cx0 = base[lane];
        float cx1 = (lane < 31) ? base[lane + 32] : NINF;
        u32 mo = __reduce_max_sync(FULL, ord_of_float(fmaxf(cx0, cx1)));
        float mx = float_of_ord(mo);
        float e0 = expf(cx0 - mx);
        float e1 = (lane < 31) ? expf(cx1 - mx) : 0.0f;
        float sm = e0 + e1;
        #pragma unroll
        for (int off = 16; off; off >>= 1)
            sm += __shfl_xor_sync(FULL, sm, off);
        float lse = logf(sm);
        lp0 = cx0 - mx - lse;
        lp1 = cx1 - mx - lse;
    }
    // prefetch frame 1
    float nx0 = base[CCC + lane];
    float nx1 = (lane < 31) ? base[CCC + lane + 32] : NINF;

    for (int t = 0; t < TT; ++t) {
        // ---- 2a: per-beam prep ----
        float lpBlank = __shfl_sync(FULL, lp1, 30);   // class 62
        int ls = (bm_last >= 0) ? (bm_last & 31) : 0;
        float v0 = __shfl_sync(FULL, lp0, ls);
        float v1 = __shfl_sync(FULL, lp1, ls);
        float lpLast = (bm_last >= 32) ? v1 : v0;

        int dup = 0;
        #pragma unroll
        for (int k = 0; k < 7; ++k) {
            u32 hk1 = __shfl_sync(FULL, bm_h1, k);
            u32 hk2 = __shfl_sync(FULL, bm_h2, k);
            if (k < lane && hk1 == bm_h1 && hk2 == bm_h2) dup = 1;
        }
        u32 dupmask = __ballot_sync(FULL, dup) & 0xFFu;

        float bm_ptot = lax_logaddexp(bm_pb, bm_pnb);
        bm_spb = bm_ptot + lpBlank;
        float bm_spnb = (bm_last >= 0) ? (bm_pnb + lpLast) : NEGF;

        // ---- 2b: inverted merge detection (dup veto via mask) ----
        int msrc = -1;
        #pragma unroll
        for (int i = 0; i < WW; ++i) {
            u32 ih1 = __shfl_sync(FULL, bm_h1, i);
            u32 ih2 = __shfl_sync(FULL, bm_h2, i);
            u32 c1 = bm_h1 - ih1 * HB1C - 1u;
            if (!((dupmask >> i) & 1u) && c1 < (u32)VVV &&
                bm_h2 == ih2 * HB2C + c1 + 1u)
                msrc = i * 64 + (int)c1;
        }
        if (dup || lane >= WW) msrc = -1;

        // kill masks: bit i -> extend (beam i, class lane[/+32]) merged or dup
        u32 killLo = dupmask, killHi = dupmask;
        #pragma unroll
        for (int j = 0; j < WW; ++j) {
            int ms = __shfl_sync(FULL, msrc, j);
            if (ms >= 0) {
                int mi = ms >> 6, mc = ms & 63;
                if (mc == lane) killLo |= 1u << mi;
                if (mc == lane + 32) killHi |= 1u << mi;
            }
        }

        // merged stay pnb
        {
            int mi = (msrc >= 0) ? (msrc >> 6) : 0;
            int mc = (msrc >= 0) ? (msrc & 63) : 0;
            float mpbv = __shfl_sync(FULL, bm_pb, mi);
            float mptv = __shfl_sync(FULL, bm_ptot, mi);
            int   mlv  = __shfl_sync(FULL, bm_last, mi);
            float w0 = __shfl_sync(FULL, lp0, mc & 31);
            float w1 = __shfl_sync(FULL, lp1, mc & 31);
            float lpc = (mc >= 32) ? w1 : w0;
            float bv = ((mc == mlv) ? mpbv : mptv) + lpc;
            bm_mpnb = (msrc >= 0) ? seg_lse2(bm_spnb, bv) : bm_spnb;
        }

        // stay key (slot 16): idx = lane (<8)
        float cs0 = dup ? NEGF : lax_logaddexp(bm_spb, bm_mpnb);
        u64 key16 = (lane < WW)
            ? (((u64)ord_of_float(cs0) << 32) |
               (u32)(((1023u << 10) + 16u) + Mlow))
            : 0ull;

        // ---- 3: extend keys + pair pre-max ----
        u64 key[16];
        #pragma unroll
        for (int i = 0; i < WW; ++i) {
            int   ilast = __shfl_sync(FULL, bm_last, i);
            float ipb   = __shfl_sync(FULL, bm_pb, i);
            float ipt   = __shfl_sync(FULL, bm_ptot, i);
            float sl = ((lane == ilast) ? ipb : ipt) + lp0;
            if ((killLo >> i) & 1u) sl = NEGF;
            u32 lowl = (u32)(((u32)(1015 - 62 * i) << 10) + (u32)i) + Mlow;
            key[i] = ((u64)ord_of_float(sl) << 32) | lowl;
            float sh = ((lane + 32 == ilast) ? ipb : ipt) + lp1;
            if ((killHi >> i) & 1u) sh = NEGF;
            u32 lowh = (u32)(((u32)(983 - 62 * i) << 10) + (u32)(i + 8)) + Mlow;
            u64 kh = ((u64)ord_of_float(sh) << 32) | lowh;
            key[i + 8] = (lane < 30) ? kh : 0ull;
        }
        u64 pn[8];
        #pragma unroll
        for (int i = 0; i < 8; ++i) pn[i] = kmax(key[i], key[i + 8]);

        // ---- 3.5: OVERLAP — softmax of frame t+1 + prefetch t+2 ----
        float lpn0, lpn1;
        {
            u32 mo = __reduce_max_sync(FULL, ord_of_float(fmaxf(nx0, nx1)));
            float mx = float_of_ord(mo);
            float e0 = expf(nx0 - mx);
            float e1 = (lane < 31) ? expf(nx1 - mx) : 0.0f;
            float sm = e0 + e1;
            #pragma unroll
            for (int off = 16; off; off >>= 1)
                sm += __shfl_xor_sync(FULL, sm, off);
            float lse = logf(sm);
            lpn0 = nx0 - mx - lse;
            lpn1 = nx1 - mx - lse;
        }
        {
            int tn = (t + 2 < TT) ? (t + 2) : (TT - 1);
            const float* nf = base + tn * CCC;
            nx0 = nf[lane];
            nx1 = (lane < 31) ? nf[lane + 32] : NINF;
        }

        // ---- 4: top-8 via pair-node tournament + 2 REDUX per pass ----
        #pragma unroll
        for (int k2 = 0; k2 < WW; ++k2) {
            u64 q0 = kmax(pn[0], pn[1]);
            u64 q1 = kmax(pn[2], pn[3]);
            u64 q2 = kmax(pn[4], pn[5]);
            u64 q3 = kmax(pn[6], pn[7]);
            u64 loc = kmax(kmax(kmax(q0, q1), kmax(q2, q3)), key16);
            u32 hi = (u32)(loc >> 32), lo = (u32)loc;
            u32 m  = __reduce_max_sync(FULL, hi);
            u32 tx = (hi == m) ? lo : 0u;
            u32 lw = __reduce_max_sync(FULL, tx);
            if (lane == k2) { sel_m = m; sel_lo = lw; }
            // uniform decode (feeds clear; last pass feeds commit via sel_lo)
            int wlane = (int)((lw >> 5) & 31u);
            int wslot = (int)(lw & 31u);
            if (lane == wlane) {
                if (wslot == 16) {
                    key16 &= 0xffffffffull;
                } else {
                    #pragma unroll
                    for (int s = 0; s < 16; ++s)
                        if (s == wslot) key[s] &= 0xffffffffull;
                    int wp = wslot & 7;
                    #pragma unroll
                    for (int i = 0; i < 8; ++i)
                        if (i == wp) pn[i] = kmax(key[i], key[i + 8]);
                }
            }
        }

        // ---- 5: commit (gathers via shfl from OLD beam regs) ----
        int idx  = 1023 - (int)(sel_lo >> 10);
        bool stay = idx < WW;
        int slot = (int)(sel_lo & 31u);
        int wl   = (int)((sel_lo >> 5) & 31u);
        int src  = stay ? idx : (slot & 7);
        int c    = wl + ((slot & 8) ? 32 : 0);
        u32 g_h1   = __shfl_sync(FULL, bm_h1, src);
        u32 g_h2   = __shfl_sync(FULL, bm_h2, src);
        int g_last = __shfl_sync(FULL, bm_last, src);
        int g_len  = __shfl_sync(FULL, bm_len, src);
        float g_spb  = __shfl_sync(FULL, bm_spb, src);
        float g_mpnb = __shfl_sync(FULL, bm_mpnb, src);
        if (lane < WW) {
            bool alive = sel_m > ordDeadThr;
            float score = float_of_ord(sel_m);
            float npb  = stay ? g_spb  : NEGF;
            float npnb = stay ? g_mpnb : score;
            if (!alive) { npb = NEGF; npnb = NEGF; }
            bm_pb = npb; bm_pnb = npnb;
            bm_h1 = stay ? g_h1 : (g_h1 * HB1C + (u32)(c + 1));
            bm_h2 = stay ? g_h2 : (g_h2 * HB2C + (u32)(c + 1));
            bm_last = stay ? g_last : c;
            bm_len  = g_len + (stay ? 0 : 1);
            hist[wip][t * WW + lane] = stay
                ? (unsigned short)(idx << 8)
                : (unsigned short)(((slot & 7) << 8) | (c + 1));
        }
        lp0 = lpn0; lp1 = lpn1;
    }

    // ---- outputs: decoded [B*128], lengths [B], prob [B], all f32 ----
    float* dec = out + (size_t)b * TT;
    #pragma unroll
    for (int s2 = 0; s2 < 4; ++s2)
        dec[lane + 32 * s2] = -1.0f;
    __syncwarp();
    int len0 = __shfl_sync(FULL, bm_len, 0);
    float pb0  = __shfl_sync(FULL, bm_pb, 0);
    float pnb0 = __shfl_sync(FULL, bm_pnb, 0);
    if (lane == 0) {
        int cur = 0;
        int pos = len0 - 1;
        for (int tt = TT - 1; tt >= 0; --tt) {
            unsigned short h = hist[wip][tt * WW + cur];
            int cc = (int)(h & 0xFF) - 1;
            cur = h >> 8;
            if (cc >= 0) dec[pos--] = (float)cc;
        }
        out[(size_t)BATCH * TT + b] = (float)len0;
        out[(size_t)BATCH * TT + BATCH + b] = expf(lax_logaddexp(pb0, pnb0));
    }
}

extern "C" void kernel_launch(void* const* d_in, const int* in_sizes, int n_in,
                              void* d_out, int out_size) {
    const float* logits = (const float*)d_in[0];
    float* out = (float*)d_out;
    ctc_beam_kernel<<<BATCH / WPB, 32 * WPB>>>(logits, out);
}